// round 7
// baseline (speedup 1.0000x reference)
#include <cuda_runtime.h>
#include <cuda_bf16.h>
#include <math.h>
#include <stdint.h>

#define S_LEN  2048
#define NHEAD  16
#define HDIM   2048
#define QLAT   1536
#define KVLAT  512
#define ROT    64
#define QK_D   192
#define V_D    128
#define CKV_W  (KVLAT + ROT)       // 576
#define QUP_W  (NHEAD * 192)       // 3072
#define KVUP_W (NHEAD * 256)       // 4096

typedef __nv_bfloat16 bf16;

// ---------------- scratch (device globals; no allocations) ----------------
__device__ float g_cq[(size_t)S_LEN * QLAT];
__device__ float g_ckv[(size_t)S_LEN * CKV_W];
__device__ float g_qup[(size_t)S_LEN * QUP_W];
__device__ float g_kvup[(size_t)S_LEN * KVUP_W];

__device__ bf16 g_hidh[(size_t)S_LEN * HDIM],  g_hidl[(size_t)S_LEN * HDIM];
__device__ bf16 g_wqdh[(size_t)QLAT * HDIM],   g_wqdl[(size_t)QLAT * HDIM];
__device__ bf16 g_wkdh[(size_t)CKV_W * HDIM],  g_wkdl[(size_t)CKV_W * HDIM];
__device__ bf16 g_wquh[(size_t)QUP_W * QLAT],  g_wqul[(size_t)QUP_W * QLAT];
__device__ bf16 g_wkuh[(size_t)KVUP_W * KVLAT],g_wkul[(size_t)KVUP_W * KVLAT];
__device__ bf16 g_woh[(size_t)HDIM * HDIM],    g_wol[(size_t)HDIM * HDIM];
__device__ bf16 g_cqh[(size_t)S_LEN * QLAT],   g_cql[(size_t)S_LEN * QLAT];
__device__ bf16 g_ckvh[(size_t)S_LEN * CKV_W], g_ckvl[(size_t)S_LEN * CKV_W];
__device__ bf16 g_Qh[(size_t)NHEAD * S_LEN * QK_D], g_Ql[(size_t)NHEAD * S_LEN * QK_D];
__device__ bf16 g_Kh[(size_t)NHEAD * S_LEN * QK_D], g_Kl[(size_t)NHEAD * S_LEN * QK_D];
__device__ bf16 g_VTh[(size_t)NHEAD * V_D * S_LEN], g_VTl[(size_t)NHEAD * V_D * S_LEN];
__device__ bf16 g_Ph[(size_t)NHEAD * S_LEN * S_LEN], g_Pl[(size_t)NHEAD * S_LEN * S_LEN];
__device__ bf16 g_aph[(size_t)S_LEN * HDIM],   g_apl[(size_t)S_LEN * HDIM];

// ---------------- helpers ----------------
__device__ __forceinline__ void split1(float v, bf16 &h, bf16 &l) {
    h = __float2bfloat16_rn(v);
    l = __float2bfloat16_rn(v - __bfloat162float(h));
}
__device__ __forceinline__ uint32_t split2(float x, float y, uint32_t &lo) {
    bf16 hx, lx, hy, ly;
    split1(x, hx, lx); split1(y, hy, ly);
    __nv_bfloat162 h2 = __halves2bfloat162(hx, hy);
    __nv_bfloat162 l2 = __halves2bfloat162(lx, ly);
    lo = *reinterpret_cast<uint32_t*>(&l2);
    return *reinterpret_cast<uint32_t*>(&h2);
}
__device__ __forceinline__ void mma_bf16(float c[4],
                                         uint32_t a0, uint32_t a1, uint32_t a2, uint32_t a3,
                                         uint32_t b0, uint32_t b1) {
    asm volatile(
        "mma.sync.aligned.m16n8k16.row.col.f32.bf16.bf16.f32 "
        "{%0,%1,%2,%3}, {%4,%5,%6,%7}, {%8,%9}, {%0,%1,%2,%3};"
        : "+f"(c[0]), "+f"(c[1]), "+f"(c[2]), "+f"(c[3])
        : "r"(a0), "r"(a1), "r"(a2), "r"(a3), "r"(b0), "r"(b1));
}
__device__ __forceinline__ void ldsm4(uint32_t &r0, uint32_t &r1, uint32_t &r2, uint32_t &r3,
                                      uint32_t addr) {
    asm volatile("ldmatrix.sync.aligned.m8n8.x4.shared.b16 {%0,%1,%2,%3}, [%4];"
                 : "=r"(r0), "=r"(r1), "=r"(r2), "=r"(r3) : "r"(addr));
}

// ---------------- split-bf16 HMMA GEMM v2 ----------------
// C[2048, N] = A * B^T ; A hi/lo [M,K] k-major, B hi/lo [N,K] k-major.
// BM=128 BN=128 BK=32, 128 threads, 4 warps (2x2), warp tile 64x64.
// 3-stage cp.async pipeline. 2 CTAs/SM.
// Optional second matrix (B2/C2) selected when bx >= n1tiles (q_down+kv_down fusion).
// EPI 0: f32 C.  EPI 1: split bf16 C. causal 1: skip bx>by. causal 2: K trim.
#define BUF_B  8192          // one 128x32 bf16 buffer
#define STG_B  32768         // 4 buffers (Ah,Al,Bh,Bl)

template<int EPI>
__global__ void __launch_bounds__(128, 2)
gemm2(const bf16* __restrict__ AhG, const bf16* __restrict__ AlG,
      const bf16* __restrict__ BhG, const bf16* __restrict__ BlG,
      float* __restrict__ CG, bf16* __restrict__ ChG, bf16* __restrict__ ClG,
      const bf16* __restrict__ B2h, const bf16* __restrict__ B2l,
      float* __restrict__ C2G,
      int n1tiles, int N1, int N2, int K,
      int lda, int ldb, int ldc, int ldb2, int ldc2,
      long long sA, long long sB, long long sC, int causal)
{
    extern __shared__ __align__(1024) uint8_t smem[];

    int bx = blockIdx.x, by = blockIdx.y, bz = blockIdx.z;
    if (causal == 1 && bx > by) return;

    const bf16* Ah = AhG + bz * sA;
    const bf16* Al = AlG + bz * sA;
    const bf16* Bh;  const bf16* Bl;
    float* C = nullptr; bf16* Ch = nullptr; bf16* Cl = nullptr;
    int n, ldbv, ldcv;
    if (bx < n1tiles) {
        Bh = BhG + bz * sB; Bl = BlG + bz * sB;
        if (EPI == 0) C = CG + bz * sC;
        else { Ch = ChG + bz * sC; Cl = ClG + bz * sC; }
        n = N1; ldbv = ldb; ldcv = ldc;
    } else {
        Bh = B2h; Bl = B2l; C = C2G;
        n = N2; ldbv = ldb2; ldcv = ldc2; bx -= n1tiles;
    }

    int Keff = K;
    if (causal == 2) { int kl = (by + 1) * 128; if (kl < Keff) Keff = kl; }
    int iters = Keff >> 5;

    int tid = threadIdx.x, lane = tid & 31, warp = tid >> 5;
    int wm = warp & 1, wn = warp >> 1;

    // ---- global load mapping: thread = one row of each buffer, 4 x 16B chunks
    const bf16* aHp = Ah + (size_t)(by * 128 + tid) * lda;
    const bf16* aLp = Al + (size_t)(by * 128 + tid) * lda;
    int gn = bx * 128 + tid;
    int bvalid = (gn < n) ? 16 : 0;
    int gcl = (gn < n) ? gn : 0;
    const bf16* bHp = Bh + (size_t)gcl * ldbv;
    const bf16* bLp = Bl + (size_t)gcl * ldbv;

    uint32_t sb = (uint32_t)__cvta_generic_to_shared(smem);
    uint32_t soff[4];
    #pragma unroll
    for (int c = 0; c < 4; c++)
        soff[c] = tid * 64 + ((c ^ ((tid >> 1) & 3)) << 4);

    auto load_stage = [&](int it, int st) {
        uint32_t base = sb + st * STG_B;
        int kb = it * 32;
        #pragma unroll
        for (int c = 0; c < 4; c++) {
            int ko = kb + c * 8;
            asm volatile("cp.async.ca.shared.global [%0], [%1], 16;"
                         :: "r"(base + soff[c]), "l"(aHp + ko));
            asm volatile("cp.async.ca.shared.global [%0], [%1], 16;"
                         :: "r"(base + BUF_B + soff[c]), "l"(aLp + ko));
            asm volatile("cp.async.ca.shared.global [%0], [%1], 16, %2;"
                         :: "r"(base + 2*BUF_B + soff[c]), "l"(bHp + ko), "r"(bvalid));
            asm volatile("cp.async.ca.shared.global [%0], [%1], 16, %2;"
                         :: "r"(base + 3*BUF_B + soff[c]), "l"(bLp + ko), "r"(bvalid));
        }
        asm volatile("cp.async.commit_group;");
    };

    // ---- fragment addressing (precomputed)
    uint32_t aAddr[4];   // per mt; add stage base + chunk swizzle at use
    int aSw[4];
    #pragma unroll
    for (int mt = 0; mt < 4; mt++) {
        int r = wm * 64 + mt * 16 + (lane & 15);
        aAddr[mt] = r * 64; aSw[mt] = (r >> 1) & 3;
    }
    uint32_t bAddr[4]; int bSw[4];
    #pragma unroll
    for (int np = 0; np < 4; np++) {
        int r = wn * 64 + np * 16 + (lane & 7) + ((lane & 16) ? 8 : 0);
        bAddr[np] = r * 64; bSw[np] = (r >> 1) & 3;
    }
    int aHalf = lane >> 4;          // 0/1: which 16B chunk within k16
    int bHalf = (lane >> 3) & 1;

    float acc[4][8][4];
    #pragma unroll
    for (int i = 0; i < 4; i++)
        #pragma unroll
        for (int j = 0; j < 8; j++)
            #pragma unroll
            for (int l = 0; l < 4; l++) acc[i][j][l] = 0.f;

    load_stage(0, 0);
    if (iters > 1) load_stage(1, 1);

    for (int it = 0; it < iters; ++it) {
        int s = it - (it / 3) * 3;
        if (it + 1 < iters) asm volatile("cp.async.wait_group 1;");
        else                asm volatile("cp.async.wait_group 0;");
        __syncthreads();
        if (it + 2 < iters) load_stage(it + 2, (it + 2) % 3);

        uint32_t Ab = sb + s * STG_B;
        uint32_t Bb = Ab + 2 * BUF_B;
        #pragma unroll
        for (int ks = 0; ks < 2; ks++) {
            uint32_t aH[4][4], aL[4][4], bH[4][4], bL[4][4];
            int ca = 2 * ks + aHalf;
            int cb = 2 * ks + bHalf;
            #pragma unroll
            for (int mt = 0; mt < 4; mt++) {
                uint32_t ad = Ab + aAddr[mt] + (((uint32_t)(ca ^ aSw[mt])) << 4);
                ldsm4(aH[mt][0], aH[mt][1], aH[mt][2], aH[mt][3], ad);
                ldsm4(aL[mt][0], aL[mt][1], aL[mt][2], aL[mt][3], ad + BUF_B);
            }
            #pragma unroll
            for (int np = 0; np < 4; np++) {
                uint32_t bd = Bb + bAddr[np] + (((uint32_t)(cb ^ bSw[np])) << 4);
                ldsm4(bH[np][0], bH[np][1], bH[np][2], bH[np][3], bd);
                ldsm4(bL[np][0], bL[np][1], bL[np][2], bL[np][3], bd + BUF_B);
            }
            // pass 1: Alo * Bhi
            #pragma unroll
            for (int mt = 0; mt < 4; mt++)
                #pragma unroll
                for (int nt = 0; nt < 8; nt++) {
                    int np = nt >> 1, hf = (nt & 1) * 2;
                    mma_bf16(acc[mt][nt], aL[mt][0], aL[mt][1], aL[mt][2], aL[mt][3],
                             bH[np][hf], bH[np][hf + 1]);
                }
            // pass 2: Ahi * Blo
            #pragma unroll
            for (int mt = 0; mt < 4; mt++)
                #pragma unroll
                for (int nt = 0; nt < 8; nt++) {
                    int np = nt >> 1, hf = (nt & 1) * 2;
                    mma_bf16(acc[mt][nt], aH[mt][0], aH[mt][1], aH[mt][2], aH[mt][3],
                             bL[np][hf], bL[np][hf + 1]);
                }
            // pass 3: Ahi * Bhi
            #pragma unroll
            for (int mt = 0; mt < 4; mt++)
                #pragma unroll
                for (int nt = 0; nt < 8; nt++) {
                    int np = nt >> 1, hf = (nt & 1) * 2;
                    mma_bf16(acc[mt][nt], aH[mt][0], aH[mt][1], aH[mt][2], aH[mt][3],
                             bH[np][hf], bH[np][hf + 1]);
                }
        }
    }

    // ---- epilogue ----
    int g = lane >> 2, tg = lane & 3;
    #pragma unroll
    for (int mt = 0; mt < 4; mt++) {
        int r0 = by * 128 + wm * 64 + mt * 16 + g;
        #pragma unroll
        for (int nt = 0; nt < 8; nt++) {
            int col = bx * 128 + wn * 64 + nt * 8 + 2 * tg;
            if (col < n) {
                if (EPI == 0) {
                    *reinterpret_cast<float2*>(C + (size_t)r0 * ldcv + col) =
                        make_float2(acc[mt][nt][0], acc[mt][nt][1]);
                    *reinterpret_cast<float2*>(C + (size_t)(r0 + 8) * ldcv + col) =
                        make_float2(acc[mt][nt][2], acc[mt][nt][3]);
                } else {
                    uint32_t lo0, lo1;
                    uint32_t hi0 = split2(acc[mt][nt][0], acc[mt][nt][1], lo0);
                    uint32_t hi1 = split2(acc[mt][nt][2], acc[mt][nt][3], lo1);
                    *reinterpret_cast<uint32_t*>(Ch + (size_t)r0 * ldcv + col) = hi0;
                    *reinterpret_cast<uint32_t*>(Cl + (size_t)r0 * ldcv + col) = lo0;
                    *reinterpret_cast<uint32_t*>(Ch + (size_t)(r0 + 8) * ldcv + col) = hi1;
                    *reinterpret_cast<uint32_t*>(Cl + (size_t)(r0 + 8) * ldcv + col) = lo1;
                }
            }
        }
    }
}

// ---------------- f32 -> split bf16 conversion ----------------
__global__ void convert_split(const float* __restrict__ s, bf16* __restrict__ h,
                              bf16* __restrict__ l, int n)
{
    int i = (blockIdx.x * 256 + threadIdx.x) * 4;
    if (i < n) {
        float4 v = *reinterpret_cast<const float4*>(s + i);
        uint32_t lo0, lo1;
        uint32_t hi0 = split2(v.x, v.y, lo0);
        uint32_t hi1 = split2(v.z, v.w, lo1);
        *reinterpret_cast<uint32_t*>(h + i)     = hi0;
        *reinterpret_cast<uint32_t*>(l + i)     = lo0;
        *reinterpret_cast<uint32_t*>(h + i + 2) = hi1;
        *reinterpret_cast<uint32_t*>(l + i + 2) = lo1;
    }
}

// ---------------- RMS norm: f32 in-place + split bf16 out ----------------
__global__ void rmsnorm_split_kernel(float* __restrict__ x, const float* __restrict__ w,
                                     bf16* __restrict__ oh, bf16* __restrict__ ol, int n)
{
    float* xr = x + (size_t)blockIdx.x * n;
    bf16* hr = oh + (size_t)blockIdx.x * n;
    bf16* lr = ol + (size_t)blockIdx.x * n;
    __shared__ float red[256];
    int t = threadIdx.x;
    float s = 0.f;
    for (int i = t; i < n; i += 256) { float v = xr[i]; s += v * v; }
    red[t] = s; __syncthreads();
    for (int k = 128; k > 0; k >>= 1) { if (t < k) red[t] += red[t + k]; __syncthreads(); }
    float inv = 1.0f / sqrtf(red[0] / (float)n + 1e-6f);
    for (int i = t; i < n; i += 256) {
        float v = w[i] * (xr[i] * inv);
        xr[i] = v;
        bf16 h, l; split1(v, h, l);
        hr[i] = h; lr[i] = l;
    }
}

// ---------------- RoPE + assemble split Q/K ----------------
__global__ void rope_assemble_kernel()
{
    int s = blockIdx.x;
    int t = threadIdx.x;
    __shared__ float cs[32], sn[32], kr[64];

    if (t < 32) {
        float invf = (float)exp(-(double)t / 32.0 * log(10000.0));
        float ang  = (float)s * invf;
        double a = (double)ang;
        float c = (float)cos(a), si = (float)sin(a);
        cs[t] = c; sn[t] = si;
        float x0 = g_ckv[(size_t)s * CKV_W + KVLAT + 2 * t];
        float x1 = g_ckv[(size_t)s * CKV_W + KVLAT + 2 * t + 1];
        kr[t]      = x0 * c - x1 * si;
        kr[t + 32] = x1 * c + x0 * si;
    }
    __syncthreads();

    for (int idx = t; idx < NHEAD * 32; idx += 256) {
        int h = idx >> 5, j = idx & 31;
        float x0 = g_qup[(size_t)s * QUP_W + h * 192 + 128 + 2 * j];
        float x1 = g_qup[(size_t)s * QUP_W + h * 192 + 128 + 2 * j + 1];
        size_t base = ((size_t)h * S_LEN + s) * QK_D;
        bf16 hh, ll;
        split1(x0 * cs[j] - x1 * sn[j], hh, ll); g_Qh[base + j] = hh;      g_Ql[base + j] = ll;
        split1(x1 * cs[j] + x0 * sn[j], hh, ll); g_Qh[base + j + 32] = hh; g_Ql[base + j + 32] = ll;
    }
    for (int idx = t; idx < NHEAD * 64; idx += 256) {
        int h = idx >> 6, j = idx & 63;
        size_t base = ((size_t)h * S_LEN + s) * QK_D;
        bf16 hh, ll; split1(kr[j], hh, ll);
        g_Kh[base + j] = hh; g_Kl[base + j] = ll;
    }
    for (int idx = t; idx < NHEAD * 128; idx += 256) {
        int h = idx >> 7, d = idx & 127;
        size_t base = ((size_t)h * S_LEN + s) * QK_D + 64 + d;
        bf16 hh, ll;
        split1(g_qup[(size_t)s * QUP_W + h * 192 + d], hh, ll);
        g_Qh[base] = hh; g_Ql[base] = ll;
        split1(g_kvup[(size_t)s * KVUP_W + h * 256 + d], hh, ll);
        g_Kh[base] = hh; g_Kl[base] = ll;
    }
}

// ---------------- V transpose + split: kvup -> VT[h][d][s] ----------------
__global__ void vt_kernel()   // grid (64, 4, 16), block (32, 8)
{
    __shared__ float tile[32][33];
    int h = blockIdx.z, s0 = blockIdx.x * 32, d0 = blockIdx.y * 32;
    int tx = threadIdx.x, ty = threadIdx.y;
    #pragma unroll
    for (int j = 0; j < 4; j++) {
        int srow = s0 + ty + 8 * j;
        tile[ty + 8 * j][tx] = g_kvup[(size_t)srow * KVUP_W + h * 256 + 128 + d0 + tx];
    }
    __syncthreads();
    #pragma unroll
    for (int j = 0; j < 4; j++) {
        int d = d0 + ty + 8 * j;
        int s = s0 + tx;
        bf16 hh, ll; split1(tile[tx][ty + 8 * j], hh, ll);
        size_t o = ((size_t)h * V_D + d) * S_LEN + s;
        g_VTh[o] = hh; g_VTl[o] = ll;
    }
}

// ---------------- causal softmax: f32 in-place + split P out ----------------
__global__ void softmax_kernel(float* __restrict__ aw)
{
    int row = blockIdx.x;
    int q = row & (S_LEN - 1);
    float* x = aw + (size_t)row * S_LEN;
    bf16* ph = g_Ph + (size_t)row * S_LEN;
    bf16* pl = g_Pl + (size_t)row * S_LEN;
    __shared__ float buf[S_LEN];
    __shared__ float red[256];
    int n = q + 1;
    int nwr = ((q >> 7) + 1) << 7;
    int t = threadIdx.x;

    float m = -1e30f;
    for (int i = t; i < n; i += 256) { float v = x[i]; buf[i] = v; m = fmaxf(m, v); }
    red[t] = m; __syncthreads();
    for (int k = 128; k > 0; k >>= 1) { if (t < k) red[t] = fmaxf(red[t], red[t + k]); __syncthreads(); }
    m = red[0]; __syncthreads();

    float s = 0.f;
    for (int i = t; i < n; i += 256) { float e = expf(buf[i] - m); buf[i] = e; s += e; }
    red[t] = s; __syncthreads();
    for (int k = 128; k > 0; k >>= 1) { if (t < k) red[t] += red[t + k]; __syncthreads(); }
    float inv = 1.0f / red[0];

    for (int i = t; i < S_LEN; i += 256) {
        float p = (i < n) ? buf[i] * inv : 0.0f;
        x[i] = p;
        if (i < nwr) { bf16 hh, ll; split1(p, hh, ll); ph[i] = hh; pl[i] = ll; }
    }
}

// ---------------- launch ----------------
extern "C" void kernel_launch(void* const* d_in, const int* in_sizes, int n_in,
                              void* d_out, int out_size)
{
    const float* hidden  = (const float*)d_in[0];
    const float* q_down  = (const float*)d_in[3];
    const float* kv_down = (const float*)d_in[4];
    const float* q_up    = (const float*)d_in[5];
    const float* k_up    = (const float*)d_in[6];
    const float* o_w     = (const float*)d_in[7];
    const float* q_norm  = (const float*)d_in[8];
    const float* kv_norm = (const float*)d_in[9];

    float* out = (float*)d_out;
    float* aw = out;
    float* ao = out + (size_t)NHEAD * S_LEN * S_LEN;

    size_t smem = 3 * STG_B;   // 96 KB
    cudaFuncSetAttribute(gemm2<0>, cudaFuncAttributeMaxDynamicSharedMemorySize, smem);
    cudaFuncSetAttribute(gemm2<1>, cudaFuncAttributeMaxDynamicSharedMemorySize, smem);

    float *cq, *ckv, *qup, *kvup;
    cudaGetSymbolAddress((void**)&cq,   g_cq);
    cudaGetSymbolAddress((void**)&ckv,  g_ckv);
    cudaGetSymbolAddress((void**)&qup,  g_qup);
    cudaGetSymbolAddress((void**)&kvup, g_kvup);
    bf16 *hidh,*hidl,*wqdh,*wqdl,*wkdh,*wkdl,*wquh,*wqul,*wkuh,*wkul,*woh,*wol;
    bf16 *cqh,*cql,*ckvh,*ckvl,*Qh,*Ql,*Kh,*Kl,*VTh,*VTl,*Ph,*Pl,*aph,*apl;
    cudaGetSymbolAddress((void**)&hidh, g_hidh); cudaGetSymbolAddress((void**)&hidl, g_hidl);
    cudaGetSymbolAddress((void**)&wqdh, g_wqdh); cudaGetSymbolAddress((void**)&wqdl, g_wqdl);
    cudaGetSymbolAddress((void**)&wkdh, g_wkdh); cudaGetSymbolAddress((void**)&wkdl, g_wkdl);
    cudaGetSymbolAddress((void**)&wquh, g_wquh); cudaGetSymbolAddress((void**)&wqul, g_wqul);
    cudaGetSymbolAddress((void**)&wkuh, g_wkuh); cudaGetSymbolAddress((void**)&wkul, g_wkul);
    cudaGetSymbolAddress((void**)&woh,  g_woh);  cudaGetSymbolAddress((void**)&wol,  g_wol);
    cudaGetSymbolAddress((void**)&cqh,  g_cqh);  cudaGetSymbolAddress((void**)&cql,  g_cql);
    cudaGetSymbolAddress((void**)&ckvh, g_ckvh); cudaGetSymbolAddress((void**)&ckvl, g_ckvl);
    cudaGetSymbolAddress((void**)&Qh,   g_Qh);   cudaGetSymbolAddress((void**)&Ql,   g_Ql);
    cudaGetSymbolAddress((void**)&Kh,   g_Kh);   cudaGetSymbolAddress((void**)&Kl,   g_Kl);
    cudaGetSymbolAddress((void**)&VTh,  g_VTh);  cudaGetSymbolAddress((void**)&VTl,  g_VTl);
    cudaGetSymbolAddress((void**)&Ph,   g_Ph);   cudaGetSymbolAddress((void**)&Pl,   g_Pl);
    cudaGetSymbolAddress((void**)&aph,  g_aph);  cudaGetSymbolAddress((void**)&apl,  g_apl);

    dim3 blk(256);
    dim3 gblk(128);
    auto cgrid = [](size_t n) { return (unsigned)((n / 4 + 255) / 256); };

    // 0) split conversions
    convert_split<<<cgrid((size_t)S_LEN*HDIM),   blk>>>(hidden,  hidh, hidl, S_LEN*HDIM);
    convert_split<<<cgrid((size_t)QLAT*HDIM),    blk>>>(q_down,  wqdh, wqdl, QLAT*HDIM);
    convert_split<<<cgrid((size_t)CKV_W*HDIM),   blk>>>(kv_down, wkdh, wkdl, CKV_W*HDIM);
    convert_split<<<cgrid((size_t)QUP_W*QLAT),   blk>>>(q_up,    wquh, wqul, QUP_W*QLAT);
    convert_split<<<cgrid((size_t)KVUP_W*KVLAT), blk>>>(k_up,    wkuh, wkul, KVUP_W*KVLAT);
    convert_split<<<cgrid((size_t)HDIM*HDIM),    blk>>>(o_w,     woh,  wol,  HDIM*HDIM);

    // 1) fused down projections: N = 1536 (12 tiles) + 576 (5 tiles)
    gemm2<0><<<dim3(17, 16), gblk, smem>>>(
        hidh, hidl, wqdh, wqdl, cq, nullptr, nullptr,
        wkdh, wkdl, ckv,
        12, QLAT, CKV_W, HDIM,
        HDIM, HDIM, QLAT, HDIM, CKV_W, 0, 0, 0, 0);

    // 2) RMS norms
    rmsnorm_split_kernel<<<S_LEN, blk>>>(cq,  q_norm,  cqh,  cql,  QLAT);
    rmsnorm_split_kernel<<<S_LEN, blk>>>(ckv, kv_norm, ckvh, ckvl, CKV_W);

    // 3) up projections (f32 out)
    gemm2<0><<<dim3(QUP_W/128, 16), gblk, smem>>>(
        cqh, cql, wquh, wqul, qup, nullptr, nullptr,
        nullptr, nullptr, nullptr,
        1 << 20, QUP_W, 0, QLAT,
        QLAT, QLAT, QUP_W, 0, 0, 0, 0, 0, 0);
    gemm2<0><<<dim3(KVUP_W/128, 16), gblk, smem>>>(
        ckvh, ckvl, wkuh, wkul, kvup, nullptr, nullptr,
        nullptr, nullptr, nullptr,
        1 << 20, KVUP_W, 0, KVLAT,
        CKV_W, KVLAT, KVUP_W, 0, 0, 0, 0, 0, 0);

    // 4) RoPE + assembly, V transpose
    rope_assemble_kernel<<<S_LEN, blk>>>();
    vt_kernel<<<dim3(64, 4, 16), dim3(32, 8)>>>();

    // 5) logits S = Q K^T (causal tile skip), f32 into d_out
    gemm2<0><<<dim3(16, 16, 16), gblk, smem>>>(
        Qh, Ql, Kh, Kl, aw, nullptr, nullptr,
        nullptr, nullptr, nullptr,
        1 << 20, S_LEN, 0, QK_D,
        QK_D, QK_D, S_LEN, 0, 0,
        (long long)S_LEN*QK_D, (long long)S_LEN*QK_D, (long long)S_LEN*S_LEN, 1);

    // 6) softmax (f32 in-place, split P out)
    softmax_kernel<<<NHEAD * S_LEN, blk>>>(aw);

    // 7) O = P @ V (split bf16 out), causal K-trim
    gemm2<1><<<dim3(1, 16, 16), gblk, smem>>>(
        Ph, Pl, VTh, VTl, nullptr, aph, apl,
        nullptr, nullptr, nullptr,
        1 << 20, V_D, 0, S_LEN,
        S_LEN, S_LEN, HDIM, 0, 0,
        (long long)S_LEN*S_LEN, (long long)V_D*S_LEN, (long long)V_D, 2);

    // 8) final output projection (f32 into d_out)
    gemm2<0><<<dim3(16, 16), gblk, smem>>>(
        aph, apl, woh, wol, ao, nullptr, nullptr,
        nullptr, nullptr, nullptr,
        1 << 20, HDIM, 0, HDIM,
        HDIM, HDIM, HDIM, 0, 0, 0, 0, 0, 0);
}

// round 8
// speedup vs baseline: 1.4422x; 1.4422x over previous
#include <cuda_runtime.h>
#include <cuda_bf16.h>
#include <math.h>
#include <stdint.h>

#define S_LEN  2048
#define NHEAD  16
#define HDIM   2048
#define QLAT   1536
#define KVLAT  512
#define ROT    64
#define QK_D   192
#define V_D    128
#define CKV_W  (KVLAT + ROT)       // 576
#define QUP_W  (NHEAD * 192)       // 3072
#define KVUP_W (NHEAD * 256)       // 4096

typedef __nv_bfloat16 bf16;

// ---------------- scratch (device globals; no allocations) ----------------
__device__ float g_cq[(size_t)S_LEN * QLAT];
__device__ float g_ckv[(size_t)S_LEN * CKV_W];
__device__ float g_qup[(size_t)S_LEN * QUP_W];
__device__ float g_kvup[(size_t)S_LEN * KVUP_W];

__device__ bf16 g_hidh[(size_t)S_LEN * HDIM],  g_hidl[(size_t)S_LEN * HDIM];
__device__ bf16 g_wqdh[(size_t)QLAT * HDIM],   g_wqdl[(size_t)QLAT * HDIM];
__device__ bf16 g_wkdh[(size_t)CKV_W * HDIM],  g_wkdl[(size_t)CKV_W * HDIM];
__device__ bf16 g_wquh[(size_t)QUP_W * QLAT],  g_wqul[(size_t)QUP_W * QLAT];
__device__ bf16 g_wkuh[(size_t)KVUP_W * KVLAT],g_wkul[(size_t)KVUP_W * KVLAT];
__device__ bf16 g_woh[(size_t)HDIM * HDIM],    g_wol[(size_t)HDIM * HDIM];
__device__ bf16 g_cqh[(size_t)S_LEN * QLAT],   g_cql[(size_t)S_LEN * QLAT];
__device__ bf16 g_ckvh[(size_t)S_LEN * CKV_W], g_ckvl[(size_t)S_LEN * CKV_W];
__device__ bf16 g_Qh[(size_t)NHEAD * S_LEN * QK_D], g_Ql[(size_t)NHEAD * S_LEN * QK_D];
__device__ bf16 g_Kh[(size_t)NHEAD * S_LEN * QK_D], g_Kl[(size_t)NHEAD * S_LEN * QK_D];
__device__ bf16 g_VTh[(size_t)NHEAD * V_D * S_LEN], g_VTl[(size_t)NHEAD * V_D * S_LEN];
__device__ bf16 g_aph[(size_t)S_LEN * HDIM],   g_apl[(size_t)S_LEN * HDIM];

// ---------------- helpers ----------------
__device__ __forceinline__ void split1(float v, bf16 &h, bf16 &l) {
    h = __float2bfloat16_rn(v);
    l = __float2bfloat16_rn(v - __bfloat162float(h));
}
__device__ __forceinline__ uint32_t split2(float x, float y, uint32_t &lo) {
    bf16 hx, lx, hy, ly;
    split1(x, hx, lx); split1(y, hy, ly);
    __nv_bfloat162 h2 = __halves2bfloat162(hx, hy);
    __nv_bfloat162 l2 = __halves2bfloat162(lx, ly);
    lo = *reinterpret_cast<uint32_t*>(&l2);
    return *reinterpret_cast<uint32_t*>(&h2);
}
__device__ __forceinline__ void mma_bf16(float c[4],
                                         uint32_t a0, uint32_t a1, uint32_t a2, uint32_t a3,
                                         uint32_t b0, uint32_t b1) {
    asm volatile(
        "mma.sync.aligned.m16n8k16.row.col.f32.bf16.bf16.f32 "
        "{%0,%1,%2,%3}, {%4,%5,%6,%7}, {%8,%9}, {%0,%1,%2,%3};"
        : "+f"(c[0]), "+f"(c[1]), "+f"(c[2]), "+f"(c[3])
        : "r"(a0), "r"(a1), "r"(a2), "r"(a3), "r"(b0), "r"(b1));
}
__device__ __forceinline__ void ldsm4(uint32_t &r0, uint32_t &r1, uint32_t &r2, uint32_t &r3,
                                      uint32_t addr) {
    asm volatile("ldmatrix.sync.aligned.m8n8.x4.shared.b16 {%0,%1,%2,%3}, [%4];"
                 : "=r"(r0), "=r"(r1), "=r"(r2), "=r"(r3) : "r"(addr));
}

// ---------------- split-bf16 HMMA GEMM (R5-proven core + 2nd-matrix fusion) ----------------
// C[2048, N] = A * B^T ; A hi/lo [M,K] k-major, B hi/lo [N,K] k-major. f32 C out.
// BM=128 BN=128 BK=64, 256 threads, 8 warps (2x4), warp tile 64x32, 2-stage cp.async.
// bx >= n1tiles selects second matrix (B2/C2). causal 1: skip bx>by.
#define TILE_BYTES 16384
#define STAGE_BYTES 65536

__global__ void __launch_bounds__(256, 1)
gemm5(const bf16* __restrict__ AhG, const bf16* __restrict__ AlG,
      const bf16* __restrict__ BhG, const bf16* __restrict__ BlG,
      float* __restrict__ CG,
      const bf16* __restrict__ B2h, const bf16* __restrict__ B2l,
      float* __restrict__ C2G,
      int n1tiles, int N1, int N2, int K,
      int lda, int ldb, int ldc, int ldb2, int ldc2,
      long long sA, long long sB, long long sC, int causal)
{
    extern __shared__ uint8_t smem[];
    int bx = blockIdx.x, by = blockIdx.y, bz = blockIdx.z;
    if (causal == 1 && bx > by) return;

    const bf16* Ah = AhG + bz * sA;
    const bf16* Al = AlG + bz * sA;
    const bf16* Bh; const bf16* Bl; float* C;
    int n, ldbv, ldcv;
    if (bx < n1tiles) {
        Bh = BhG + bz * sB; Bl = BlG + bz * sB; C = CG + bz * sC;
        n = N1; ldbv = ldb; ldcv = ldc;
    } else {
        bx -= n1tiles;
        Bh = B2h; Bl = B2l; C = C2G;
        n = N2; ldbv = ldb2; ldcv = ldc2;
    }

    int iters = K >> 6;

    int tid = threadIdx.x, lane = tid & 31, warp = tid >> 5;
    int wm = warp & 1, wn = warp >> 1;

    int lrow = tid >> 1;
    int lc4  = (tid & 1) * 4;
    const bf16* aHp = Ah + (size_t)(by * 128 + lrow) * lda;
    const bf16* aLp = Al + (size_t)(by * 128 + lrow) * lda;
    int gn = bx * 128 + lrow;
    int bvalid = (gn < n) ? 16 : 0;
    int gcl = (gn < n) ? gn : 0;
    const bf16* bHp = Bh + (size_t)gcl * ldbv;
    const bf16* bLp = Bl + (size_t)gcl * ldbv;

    uint32_t sb = (uint32_t)__cvta_generic_to_shared(smem);
    uint32_t soff[4];
    #pragma unroll
    for (int c = 0; c < 4; c++)
        soff[c] = lrow * 128 + (((lc4 + c) ^ (lrow & 7)) << 4);

    auto load_stage = [&](int kb, int st) {
        uint32_t base = sb + st * STAGE_BYTES;
        #pragma unroll
        for (int c = 0; c < 4; c++) {
            int ko = kb + (lc4 + c) * 8;
            asm volatile("cp.async.ca.shared.global [%0], [%1], 16;"
                         :: "r"(base + soff[c]), "l"(aHp + ko));
            asm volatile("cp.async.ca.shared.global [%0], [%1], 16;"
                         :: "r"(base + TILE_BYTES + soff[c]), "l"(aLp + ko));
            asm volatile("cp.async.ca.shared.global [%0], [%1], 16, %2;"
                         :: "r"(base + 2*TILE_BYTES + soff[c]), "l"(bHp + ko), "r"(bvalid));
            asm volatile("cp.async.ca.shared.global [%0], [%1], 16, %2;"
                         :: "r"(base + 3*TILE_BYTES + soff[c]), "l"(bLp + ko), "r"(bvalid));
        }
        asm volatile("cp.async.commit_group;");
    };

    uint32_t aOff[4]; int aSw[4];
    #pragma unroll
    for (int mt = 0; mt < 4; mt++) {
        int r = wm * 64 + mt * 16 + (lane & 15);
        aOff[mt] = r * 128; aSw[mt] = r & 7;
    }
    uint32_t bOff[2]; int bSw[2];
    #pragma unroll
    for (int np = 0; np < 2; np++) {
        int r = wn * 32 + np * 16 + (lane & 7) + ((lane & 16) ? 8 : 0);
        bOff[np] = r * 128; bSw[np] = r & 7;
    }
    int aHalf = lane >> 4;
    int bHalf = (lane >> 3) & 1;

    float acc[4][4][4] = {};

    load_stage(0, 0);
    int st = 0;
    for (int it = 0; it < iters; ++it) {
        asm volatile("cp.async.wait_group 0;");
        __syncthreads();
        if (it + 1 < iters) load_stage((it + 1) * 64, st ^ 1);

        uint32_t Ab = sb + st * STAGE_BYTES;
        uint32_t Bb = Ab + 2 * TILE_BYTES;
        #pragma unroll
        for (int ks = 0; ks < 4; ks++) {
            uint32_t aHf[4][4], aLf[4][4], bHf[2][4], bLf[2][4];
            int ca = 2 * ks + aHalf;
            int cb = 2 * ks + bHalf;
            #pragma unroll
            for (int mt = 0; mt < 4; mt++) {
                uint32_t ad = Ab + aOff[mt] + (((uint32_t)(ca ^ aSw[mt])) << 4);
                ldsm4(aHf[mt][0], aHf[mt][1], aHf[mt][2], aHf[mt][3], ad);
                ldsm4(aLf[mt][0], aLf[mt][1], aLf[mt][2], aLf[mt][3], ad + TILE_BYTES);
            }
            #pragma unroll
            for (int np = 0; np < 2; np++) {
                uint32_t bd = Bb + bOff[np] + (((uint32_t)(cb ^ bSw[np])) << 4);
                ldsm4(bHf[np][0], bHf[np][1], bHf[np][2], bHf[np][3], bd);
                ldsm4(bLf[np][0], bLf[np][1], bLf[np][2], bLf[np][3], bd + TILE_BYTES);
            }
            #pragma unroll
            for (int mt = 0; mt < 4; mt++)
                #pragma unroll
                for (int nt = 0; nt < 4; nt++) {
                    int np = nt >> 1, hf = (nt & 1) * 2;
                    mma_bf16(acc[mt][nt], aLf[mt][0], aLf[mt][1], aLf[mt][2], aLf[mt][3],
                             bHf[np][hf], bHf[np][hf + 1]);
                }
            #pragma unroll
            for (int mt = 0; mt < 4; mt++)
                #pragma unroll
                for (int nt = 0; nt < 4; nt++) {
                    int np = nt >> 1, hf = (nt & 1) * 2;
                    mma_bf16(acc[mt][nt], aHf[mt][0], aHf[mt][1], aHf[mt][2], aHf[mt][3],
                             bLf[np][hf], bLf[np][hf + 1]);
                }
            #pragma unroll
            for (int mt = 0; mt < 4; mt++)
                #pragma unroll
                for (int nt = 0; nt < 4; nt++) {
                    int np = nt >> 1, hf = (nt & 1) * 2;
                    mma_bf16(acc[mt][nt], aHf[mt][0], aHf[mt][1], aHf[mt][2], aHf[mt][3],
                             bHf[np][hf], bHf[np][hf + 1]);
                }
        }
        __syncthreads();
        st ^= 1;
    }

    int g = lane >> 2, tg = lane & 3;
    #pragma unroll
    for (int mt = 0; mt < 4; mt++) {
        int r0 = by * 128 + wm * 64 + mt * 16 + g;
        #pragma unroll
        for (int nt = 0; nt < 4; nt++) {
            int col = bx * 128 + wn * 32 + nt * 8 + 2 * tg;
            if (col < n) {
                *reinterpret_cast<float2*>(C + (size_t)r0 * ldcv + col) =
                    make_float2(acc[mt][nt][0], acc[mt][nt][1]);
                *reinterpret_cast<float2*>(C + (size_t)(r0 + 8) * ldcv + col) =
                    make_float2(acc[mt][nt][2], acc[mt][nt][3]);
            }
        }
    }
}

// ---------------- PV GEMM: A = f32 P (inline split), B = split VT, C = split bf16 ----------------
// O[128q, 128d] per (row-block, head). BK=32, 256 threads, warp tile 64x32, 2-stage B.
#define PVBUF 8192
#define PVSTG 32768

__global__ void __launch_bounds__(256, 1)
gemm_pv(const float* __restrict__ Pf, const bf16* __restrict__ VThG,
        const bf16* __restrict__ VTlG, bf16* __restrict__ ChG, bf16* __restrict__ ClG)
{
    extern __shared__ uint8_t smem[];
    int by = blockIdx.x, h = blockIdx.y;

    const float* P  = Pf  + (size_t)h * S_LEN * S_LEN;
    const bf16* VTh = VThG + (size_t)h * V_D * S_LEN;
    const bf16* VTl = VTlG + (size_t)h * V_D * S_LEN;
    bf16* Ch = ChG + h * V_D;
    bf16* Cl = ClG + h * V_D;

    int iters = (by + 1) * 4;          // Keff = (by+1)*128, BK=32

    int tid = threadIdx.x, lane = tid & 31, warp = tid >> 5;
    int wm = warp & 1, wn = warp >> 1;

    // A: row = tid>>1 (0..127), cols (tid&1)*16 .. +15 (f32)
    int a_row = tid >> 1;
    int a_c0  = (tid & 1) * 16;
    const float* aP = P + (size_t)(by * 128 + a_row) * S_LEN + a_c0;
    // B: row d = tid>>1 (0..127), 2 chunks of 16B at (tid&1)*2
    int b_row = tid >> 1;
    int b_ch0 = (tid & 1) * 2;
    const bf16* bHp = VTh + (size_t)b_row * S_LEN;
    const bf16* bLp = VTl + (size_t)b_row * S_LEN;

    uint32_t sb = (uint32_t)__cvta_generic_to_shared(smem);
    int aswz = (a_row >> 1) & 3;
    int bswz = (b_row >> 1) & 3;
    uint32_t bso[2];
    #pragma unroll
    for (int c = 0; c < 2; c++)
        bso[c] = b_row * 64 + (((b_ch0 + c) ^ bswz) << 4);

    auto loadB = [&](int it, int st) {
        uint32_t base = sb + st * PVSTG + 2 * PVBUF;
        int ko = it * 32 + b_ch0 * 8;
        asm volatile("cp.async.ca.shared.global [%0], [%1], 16;"
                     :: "r"(base + bso[0]), "l"(bHp + ko));
        asm volatile("cp.async.ca.shared.global [%0], [%1], 16;"
                     :: "r"(base + bso[0] + PVBUF), "l"(bLp + ko));
        asm volatile("cp.async.ca.shared.global [%0], [%1], 16;"
                     :: "r"(base + bso[1]), "l"(bHp + ko + 8));
        asm volatile("cp.async.ca.shared.global [%0], [%1], 16;"
                     :: "r"(base + bso[1] + PVBUF), "l"(bLp + ko + 8));
        asm volatile("cp.async.commit_group;");
    };

    // fragment addressing (64B rows)
    uint32_t aOff[4]; int aSw[4];
    #pragma unroll
    for (int mt = 0; mt < 4; mt++) {
        int r = wm * 64 + mt * 16 + (lane & 15);
        aOff[mt] = r * 64; aSw[mt] = (r >> 1) & 3;
    }
    uint32_t bOff[2]; int bSw[2];
    #pragma unroll
    for (int np = 0; np < 2; np++) {
        int r = wn * 32 + np * 16 + (lane & 7) + ((lane & 16) ? 8 : 0);
        bOff[np] = r * 64; bSw[np] = (r >> 1) & 3;
    }
    int aHalf = lane >> 4;
    int bHalf = (lane >> 3) & 1;

    float acc[4][4][4] = {};
    float4 ar[4];

    loadB(0, 0);
    #pragma unroll
    for (int v = 0; v < 4; v++)
        ar[v] = *reinterpret_cast<const float4*>(aP + v * 4);

    for (int it = 0; it < iters; ++it) {
        int s = it & 1;
        __syncthreads();             // stage s free (prev compute done)
        // STS A (split)
        {
            uint32_t abase = sb + s * PVSTG;
            uint32_t hi[8], lo[8];
            #pragma unroll
            for (int v = 0; v < 4; v++) {
                hi[2*v]   = split2(ar[v].x, ar[v].y, lo[2*v]);
                hi[2*v+1] = split2(ar[v].z, ar[v].w, lo[2*v+1]);
            }
            int ch0 = a_c0 >> 3;     // 2 chunks of 16B
            #pragma unroll
            for (int c = 0; c < 2; c++) {
                uint32_t ad = abase + a_row * 64 + (((ch0 + c) ^ aswz) << 4);
                asm volatile("st.shared.v4.b32 [%0], {%1,%2,%3,%4};"
                             :: "r"(ad), "r"(hi[4*c]), "r"(hi[4*c+1]),
                                "r"(hi[4*c+2]), "r"(hi[4*c+3]));
                asm volatile("st.shared.v4.b32 [%0], {%1,%2,%3,%4};"
                             :: "r"(ad + PVBUF), "r"(lo[4*c]), "r"(lo[4*c+1]),
                                "r"(lo[4*c+2]), "r"(lo[4*c+3]));
            }
        }
        if (it + 1 < iters) {
            loadB(it + 1, s ^ 1);
            #pragma unroll
            for (int v = 0; v < 4; v++)
                ar[v] = *reinterpret_cast<const float4*>(aP + (it + 1) * 32 + v * 4);
            asm volatile("cp.async.wait_group 1;");
        } else {
            asm volatile("cp.async.wait_group 0;");
        }
        __syncthreads();

        uint32_t Ab = sb + s * PVSTG;
        uint32_t Bb = Ab + 2 * PVBUF;
        #pragma unroll
        for (int ks = 0; ks < 2; ks++) {
            uint32_t aH[4][4], aL[4][4], bH[2][4], bL[2][4];
            int ca = 2 * ks + aHalf;
            int cb = 2 * ks + bHalf;
            #pragma unroll
            for (int mt = 0; mt < 4; mt++) {
                uint32_t ad = Ab + aOff[mt] + (((uint32_t)(ca ^ aSw[mt])) << 4);
                ldsm4(aH[mt][0], aH[mt][1], aH[mt][2], aH[mt][3], ad);
                ldsm4(aL[mt][0], aL[mt][1], aL[mt][2], aL[mt][3], ad + PVBUF);
            }
            #pragma unroll
            for (int np = 0; np < 2; np++) {
                uint32_t bd = Bb + bOff[np] + (((uint32_t)(cb ^ bSw[np])) << 4);
                ldsm4(bH[np][0], bH[np][1], bH[np][2], bH[np][3], bd);
                ldsm4(bL[np][0], bL[np][1], bL[np][2], bL[np][3], bd + PVBUF);
            }
            #pragma unroll
            for (int mt = 0; mt < 4; mt++)
                #pragma unroll
                for (int nt = 0; nt < 4; nt++) {
                    int np = nt >> 1, hf = (nt & 1) * 2;
                    mma_bf16(acc[mt][nt], aL[mt][0], aL[mt][1], aL[mt][2], aL[mt][3],
                             bH[np][hf], bH[np][hf + 1]);
                }
            #pragma unroll
            for (int mt = 0; mt < 4; mt++)
                #pragma unroll
                for (int nt = 0; nt < 4; nt++) {
                    int np = nt >> 1, hf = (nt & 1) * 2;
                    mma_bf16(acc[mt][nt], aH[mt][0], aH[mt][1], aH[mt][2], aH[mt][3],
                             bL[np][hf], bL[np][hf + 1]);
                }
            #pragma unroll
            for (int mt = 0; mt < 4; mt++)
                #pragma unroll
                for (int nt = 0; nt < 4; nt++) {
                    int np = nt >> 1, hf = (nt & 1) * 2;
                    mma_bf16(acc[mt][nt], aH[mt][0], aH[mt][1], aH[mt][2], aH[mt][3],
                             bH[np][hf], bH[np][hf + 1]);
                }
        }
    }

    int g = lane >> 2, tg = lane & 3;
    #pragma unroll
    for (int mt = 0; mt < 4; mt++) {
        int r0 = by * 128 + wm * 64 + mt * 16 + g;
        #pragma unroll
        for (int nt = 0; nt < 4; nt++) {
            int col = wn * 32 + nt * 8 + 2 * tg;
            uint32_t lo0, lo1;
            uint32_t hi0 = split2(acc[mt][nt][0], acc[mt][nt][1], lo0);
            uint32_t hi1 = split2(acc[mt][nt][2], acc[mt][nt][3], lo1);
            *reinterpret_cast<uint32_t*>(Ch + (size_t)r0 * HDIM + col) = hi0;
            *reinterpret_cast<uint32_t*>(Cl + (size_t)r0 * HDIM + col) = lo0;
            *reinterpret_cast<uint32_t*>(Ch + (size_t)(r0 + 8) * HDIM + col) = hi1;
            *reinterpret_cast<uint32_t*>(Cl + (size_t)(r0 + 8) * HDIM + col) = lo1;
        }
    }
}

// ---------------- f32 -> split bf16 conversion ----------------
__global__ void convert_split(const float* __restrict__ s, bf16* __restrict__ h,
                              bf16* __restrict__ l, int n)
{
    int i = (blockIdx.x * 256 + threadIdx.x) * 4;
    if (i < n) {
        float4 v = *reinterpret_cast<const float4*>(s + i);
        uint32_t lo0, lo1;
        uint32_t hi0 = split2(v.x, v.y, lo0);
        uint32_t hi1 = split2(v.z, v.w, lo1);
        *reinterpret_cast<uint32_t*>(h + i)     = hi0;
        *reinterpret_cast<uint32_t*>(l + i)     = lo0;
        *reinterpret_cast<uint32_t*>(h + i + 2) = hi1;
        *reinterpret_cast<uint32_t*>(l + i + 2) = lo1;
    }
}

// ---------------- RMS norm: f32 in-place + split bf16 out ----------------
__global__ void rmsnorm_split_kernel(float* __restrict__ x, const float* __restrict__ w,
                                     bf16* __restrict__ oh, bf16* __restrict__ ol, int n)
{
    float* xr = x + (size_t)blockIdx.x * n;
    bf16* hr = oh + (size_t)blockIdx.x * n;
    bf16* lr = ol + (size_t)blockIdx.x * n;
    __shared__ float red[256];
    int t = threadIdx.x;
    float s = 0.f;
    for (int i = t; i < n; i += 256) { float v = xr[i]; s += v * v; }
    red[t] = s; __syncthreads();
    for (int k = 128; k > 0; k >>= 1) { if (t < k) red[t] += red[t + k]; __syncthreads(); }
    float inv = 1.0f / sqrtf(red[0] / (float)n + 1e-6f);
    for (int i = t; i < n; i += 256) {
        float v = w[i] * (xr[i] * inv);
        xr[i] = v;
        bf16 h, l; split1(v, h, l);
        hr[i] = h; lr[i] = l;
    }
}

// ---------------- RoPE + assemble split Q/K ----------------
__global__ void rope_assemble_kernel()
{
    int s = blockIdx.x;
    int t = threadIdx.x;
    __shared__ float cs[32], sn[32], kr[64];

    if (t < 32) {
        float invf = (float)exp(-(double)t / 32.0 * log(10000.0));
        float ang  = (float)s * invf;
        double a = (double)ang;
        float c = (float)cos(a), si = (float)sin(a);
        cs[t] = c; sn[t] = si;
        float x0 = g_ckv[(size_t)s * CKV_W + KVLAT + 2 * t];
        float x1 = g_ckv[(size_t)s * CKV_W + KVLAT + 2 * t + 1];
        kr[t]      = x0 * c - x1 * si;
        kr[t + 32] = x1 * c + x0 * si;
    }
    __syncthreads();

    for (int idx = t; idx < NHEAD * 32; idx += 256) {
        int h = idx >> 5, j = idx & 31;
        float x0 = g_qup[(size_t)s * QUP_W + h * 192 + 128 + 2 * j];
        float x1 = g_qup[(size_t)s * QUP_W + h * 192 + 128 + 2 * j + 1];
        size_t base = ((size_t)h * S_LEN + s) * QK_D;
        bf16 hh, ll;
        split1(x0 * cs[j] - x1 * sn[j], hh, ll); g_Qh[base + j] = hh;      g_Ql[base + j] = ll;
        split1(x1 * cs[j] + x0 * sn[j], hh, ll); g_Qh[base + j + 32] = hh; g_Ql[base + j + 32] = ll;
    }
    for (int idx = t; idx < NHEAD * 64; idx += 256) {
        int h = idx >> 6, j = idx & 63;
        size_t base = ((size_t)h * S_LEN + s) * QK_D;
        bf16 hh, ll; split1(kr[j], hh, ll);
        g_Kh[base + j] = hh; g_Kl[base + j] = ll;
    }
    for (int idx = t; idx < NHEAD * 128; idx += 256) {
        int h = idx >> 7, d = idx & 127;
        size_t base = ((size_t)h * S_LEN + s) * QK_D + 64 + d;
        bf16 hh, ll;
        split1(g_qup[(size_t)s * QUP_W + h * 192 + d], hh, ll);
        g_Qh[base] = hh; g_Ql[base] = ll;
        split1(g_kvup[(size_t)s * KVUP_W + h * 256 + d], hh, ll);
        g_Kh[base] = hh; g_Kl[base] = ll;
    }
}

// ---------------- V transpose + split: kvup -> VT[h][d][s] ----------------
__global__ void vt_kernel()   // grid (64, 4, 16), block (32, 8)
{
    __shared__ float tile[32][33];
    int h = blockIdx.z, s0 = blockIdx.x * 32, d0 = blockIdx.y * 32;
    int tx = threadIdx.x, ty = threadIdx.y;
    #pragma unroll
    for (int j = 0; j < 4; j++) {
        int srow = s0 + ty + 8 * j;
        tile[ty + 8 * j][tx] = g_kvup[(size_t)srow * KVUP_W + h * 256 + 128 + d0 + tx];
    }
    __syncthreads();
    #pragma unroll
    for (int j = 0; j < 4; j++) {
        int d = d0 + ty + 8 * j;
        int s = s0 + tx;
        bf16 hh, ll; split1(tile[tx][ty + 8 * j], hh, ll);
        size_t o = ((size_t)h * V_D + d) * S_LEN + s;
        g_VTh[o] = hh; g_VTl[o] = ll;
    }
}

// ---------------- causal softmax: f32 in-place, vectorized ----------------
__global__ void softmax_kernel(float* __restrict__ aw)
{
    int row = blockIdx.x;
    int q = row & (S_LEN - 1);
    float* x = aw + (size_t)row * S_LEN;
    __shared__ float buf[S_LEN];
    __shared__ float red[8];
    int n = q + 1;
    int n4 = n & ~3;
    int t = threadIdx.x;
    int lane = t & 31, wrp = t >> 5;

    float m = -1e30f;
    for (int i = 4 * t; i < n4; i += 1024) {
        float4 v = *reinterpret_cast<const float4*>(x + i);
        *reinterpret_cast<float4*>(buf + i) = v;
        m = fmaxf(m, fmaxf(fmaxf(v.x, v.y), fmaxf(v.z, v.w)));
    }
    for (int i = n4 + t; i < n; i += 256) { float v = x[i]; buf[i] = v; m = fmaxf(m, v); }
    #pragma unroll
    for (int o = 16; o > 0; o >>= 1) m = fmaxf(m, __shfl_xor_sync(0xffffffffu, m, o));
    if (lane == 0) red[wrp] = m;
    __syncthreads();
    m = red[lane & 7];
    #pragma unroll
    for (int o = 4; o > 0; o >>= 1) m = fmaxf(m, __shfl_xor_sync(0xffffffffu, m, o));
    __syncthreads();

    float s = 0.f;
    for (int i = 4 * t; i < n4; i += 1024) {
        float4 v = *reinterpret_cast<float4*>(buf + i);
        v.x = expf(v.x - m); v.y = expf(v.y - m);
        v.z = expf(v.z - m); v.w = expf(v.w - m);
        *reinterpret_cast<float4*>(buf + i) = v;
        s += v.x + v.y + v.z + v.w;
    }
    for (int i = n4 + t; i < n; i += 256) { float e = expf(buf[i] - m); buf[i] = e; s += e; }
    #pragma unroll
    for (int o = 16; o > 0; o >>= 1) s += __shfl_xor_sync(0xffffffffu, s, o);
    if (lane == 0) red[wrp] = s;
    __syncthreads();
    s = red[lane & 7];
    #pragma unroll
    for (int o = 4; o > 0; o >>= 1) s += __shfl_xor_sync(0xffffffffu, s, o);
    float inv = 1.0f / s;

    for (int i = 4 * t; i < S_LEN; i += 1024) {
        float4 v = *reinterpret_cast<float4*>(buf + i);
        float4 p;
        p.x = (i     < n) ? v.x * inv : 0.0f;
        p.y = (i + 1 < n) ? v.y * inv : 0.0f;
        p.z = (i + 2 < n) ? v.z * inv : 0.0f;
        p.w = (i + 3 < n) ? v.w * inv : 0.0f;
        *reinterpret_cast<float4*>(x + i) = p;
    }
}

// ---------------- launch ----------------
extern "C" void kernel_launch(void* const* d_in, const int* in_sizes, int n_in,
                              void* d_out, int out_size)
{
    const float* hidden  = (const float*)d_in[0];
    const float* q_down  = (const float*)d_in[3];
    const float* kv_down = (const float*)d_in[4];
    const float* q_up    = (const float*)d_in[5];
    const float* k_up    = (const float*)d_in[6];
    const float* o_w     = (const float*)d_in[7];
    const float* q_norm  = (const float*)d_in[8];
    const float* kv_norm = (const float*)d_in[9];

    float* out = (float*)d_out;
    float* aw = out;
    float* ao = out + (size_t)NHEAD * S_LEN * S_LEN;

    size_t smem = 2 * STAGE_BYTES;
    cudaFuncSetAttribute(gemm5, cudaFuncAttributeMaxDynamicSharedMemorySize, smem);
    cudaFuncSetAttribute(gemm_pv, cudaFuncAttributeMaxDynamicSharedMemorySize, 2 * PVSTG);

    float *cq, *ckv, *qup, *kvup;
    cudaGetSymbolAddress((void**)&cq,   g_cq);
    cudaGetSymbolAddress((void**)&ckv,  g_ckv);
    cudaGetSymbolAddress((void**)&qup,  g_qup);
    cudaGetSymbolAddress((void**)&kvup, g_kvup);
    bf16 *hidh,*hidl,*wqdh,*wqdl,*wkdh,*wkdl,*wquh,*wqul,*wkuh,*wkul,*woh,*wol;
    bf16 *cqh,*cql,*ckvh,*ckvl,*Qh,*Ql,*Kh,*Kl,*VTh,*VTl,*aph,*apl;
    cudaGetSymbolAddress((void**)&hidh, g_hidh); cudaGetSymbolAddress((void**)&hidl, g_hidl);
    cudaGetSymbolAddress((void**)&wqdh, g_wqdh); cudaGetSymbolAddress((void**)&wqdl, g_wqdl);
    cudaGetSymbolAddress((void**)&wkdh, g_wkdh); cudaGetSymbolAddress((void**)&wkdl, g_wkdl);
    cudaGetSymbolAddress((void**)&wquh, g_wquh); cudaGetSymbolAddress((void**)&wqul, g_wqul);
    cudaGetSymbolAddress((void**)&wkuh, g_wkuh); cudaGetSymbolAddress((void**)&wkul, g_wkul);
    cudaGetSymbolAddress((void**)&woh,  g_woh);  cudaGetSymbolAddress((void**)&wol,  g_wol);
    cudaGetSymbolAddress((void**)&cqh,  g_cqh);  cudaGetSymbolAddress((void**)&cql,  g_cql);
    cudaGetSymbolAddress((void**)&ckvh, g_ckvh); cudaGetSymbolAddress((void**)&ckvl, g_ckvl);
    cudaGetSymbolAddress((void**)&Qh,   g_Qh);   cudaGetSymbolAddress((void**)&Ql,   g_Ql);
    cudaGetSymbolAddress((void**)&Kh,   g_Kh);   cudaGetSymbolAddress((void**)&Kl,   g_Kl);
    cudaGetSymbolAddress((void**)&VTh,  g_VTh);  cudaGetSymbolAddress((void**)&VTl,  g_VTl);
    cudaGetSymbolAddress((void**)&aph,  g_aph);  cudaGetSymbolAddress((void**)&apl,  g_apl);

    dim3 blk(256);
    auto cgrid = [](size_t n) { return (unsigned)((n / 4 + 255) / 256); };

    // 0) split conversions
    convert_split<<<cgrid((size_t)S_LEN*HDIM),   blk>>>(hidden,  hidh, hidl, S_LEN*HDIM);
    convert_split<<<cgrid((size_t)QLAT*HDIM),    blk>>>(q_down,  wqdh, wqdl, QLAT*HDIM);
    convert_split<<<cgrid((size_t)CKV_W*HDIM),   blk>>>(kv_down, wkdh, wkdl, CKV_W*HDIM);
    convert_split<<<cgrid((size_t)QUP_W*QLAT),   blk>>>(q_up,    wquh, wqul, QUP_W*QLAT);
    convert_split<<<cgrid((size_t)KVUP_W*KVLAT), blk>>>(k_up,    wkuh, wkul, KVUP_W*KVLAT);
    convert_split<<<cgrid((size_t)HDIM*HDIM),    blk>>>(o_w,     woh,  wol,  HDIM*HDIM);

    // 1) fused down projections (q_down 12 tiles + kv_down 5 tiles)
    gemm5<<<dim3(17, 16), blk, smem>>>(
        hidh, hidl, wqdh, wqdl, cq,
        wkdh, wkdl, ckv,
        12, QLAT, CKV_W, HDIM,
        HDIM, HDIM, QLAT, HDIM, CKV_W, 0, 0, 0, 0);

    // 2) RMS norms
    rmsnorm_split_kernel<<<S_LEN, blk>>>(cq,  q_norm,  cqh,  cql,  QLAT);
    rmsnorm_split_kernel<<<S_LEN, blk>>>(ckv, kv_norm, ckvh, ckvl, CKV_W);

    // 3) up projections
    gemm5<<<dim3(QUP_W/128, 16), blk, smem>>>(
        cqh, cql, wquh, wqul, qup,
        nullptr, nullptr, nullptr,
        1 << 20, QUP_W, 0, QLAT,
        QLAT, QLAT, QUP_W, 0, 0, 0, 0, 0, 0);
    gemm5<<<dim3(KVUP_W/128, 16), blk, smem>>>(
        ckvh, ckvl, wkuh, wkul, kvup,
        nullptr, nullptr, nullptr,
        1 << 20, KVUP_W, 0, KVLAT,
        CKV_W, KVLAT, KVUP_W, 0, 0, 0, 0, 0, 0);

    // 4) RoPE + assembly, V transpose
    rope_assemble_kernel<<<S_LEN, blk>>>();
    vt_kernel<<<dim3(64, 4, 16), dim3(32, 8)>>>();

    // 5) logits S = Q K^T (causal tile skip), f32 into d_out
    gemm5<<<dim3(16, 16, 16), blk, smem>>>(
        Qh, Ql, Kh, Kl, aw,
        nullptr, nullptr, nullptr,
        1 << 20, S_LEN, 0, QK_D,
        QK_D, QK_D, S_LEN, 0, 0,
        (long long)S_LEN*QK_D, (long long)S_LEN*QK_D, (long long)S_LEN*S_LEN, 1);

    // 6) softmax (f32 in-place, vectorized)
    softmax_kernel<<<NHEAD * S_LEN, blk>>>(aw);

    // 7) O = P @ V: read f32 P, inline split, split bf16 out
    gemm_pv<<<dim3(16, 16), blk, 2 * PVSTG>>>(aw, VTh, VTl, aph, apl);

    // 8) final output projection (f32 into d_out)
    gemm5<<<dim3(16, 16), blk, smem>>>(
        aph, apl, woh, wol, ao,
        nullptr, nullptr, nullptr,
        1 << 20, HDIM, 0, HDIM,
        HDIM, HDIM, HDIM, 0, 0, 0, 0, 0, 0);
}

// round 9
// speedup vs baseline: 1.5009x; 1.0407x over previous
#include <cuda_runtime.h>
#include <cuda_bf16.h>
#include <math.h>
#include <stdint.h>

#define S_LEN  2048
#define NHEAD  16
#define HDIM   2048
#define QLAT   1536
#define KVLAT  512
#define ROT    64
#define QK_D   192
#define V_D    128
#define CKV_W  (KVLAT + ROT)       // 576
#define QUP_W  (NHEAD * 192)       // 3072
#define KVUP_W (NHEAD * 256)       // 4096

typedef __nv_bfloat16 bf16;

// ---------------- scratch (device globals; no allocations) ----------------
__device__ float g_cq[(size_t)S_LEN * QLAT];
__device__ float g_ckv[(size_t)S_LEN * CKV_W];
__device__ float g_qup[(size_t)S_LEN * QUP_W];
__device__ float g_kvup[(size_t)S_LEN * KVUP_W];

__device__ bf16 g_hidh[(size_t)S_LEN * HDIM],  g_hidl[(size_t)S_LEN * HDIM];
__device__ bf16 g_wqdh[(size_t)QLAT * HDIM],   g_wqdl[(size_t)QLAT * HDIM];
__device__ bf16 g_wkdh[(size_t)CKV_W * HDIM],  g_wkdl[(size_t)CKV_W * HDIM];
__device__ bf16 g_wquh[(size_t)QUP_W * QLAT],  g_wqul[(size_t)QUP_W * QLAT];
__device__ bf16 g_wkuh[(size_t)KVUP_W * KVLAT],g_wkul[(size_t)KVUP_W * KVLAT];
__device__ bf16 g_woh[(size_t)HDIM * HDIM],    g_wol[(size_t)HDIM * HDIM];
__device__ bf16 g_cqh[(size_t)S_LEN * QLAT],   g_cql[(size_t)S_LEN * QLAT];
__device__ bf16 g_ckvh[(size_t)S_LEN * CKV_W], g_ckvl[(size_t)S_LEN * CKV_W];
__device__ bf16 g_Qh[(size_t)NHEAD * S_LEN * QK_D], g_Ql[(size_t)NHEAD * S_LEN * QK_D];
__device__ bf16 g_Kh[(size_t)NHEAD * S_LEN * QK_D], g_Kl[(size_t)NHEAD * S_LEN * QK_D];
__device__ bf16 g_VTh[(size_t)NHEAD * V_D * S_LEN], g_VTl[(size_t)NHEAD * V_D * S_LEN];
__device__ bf16 g_aph[(size_t)S_LEN * HDIM],   g_apl[(size_t)S_LEN * HDIM];

// ---------------- helpers ----------------
__device__ __forceinline__ void split1(float v, bf16 &h, bf16 &l) {
    h = __float2bfloat16_rn(v);
    l = __float2bfloat16_rn(v - __bfloat162float(h));
}
__device__ __forceinline__ uint32_t split2(float x, float y, uint32_t &lo) {
    bf16 hx, lx, hy, ly;
    split1(x, hx, lx); split1(y, hy, ly);
    __nv_bfloat162 h2 = __halves2bfloat162(hx, hy);
    __nv_bfloat162 l2 = __halves2bfloat162(lx, ly);
    lo = *reinterpret_cast<uint32_t*>(&l2);
    return *reinterpret_cast<uint32_t*>(&h2);
}
__device__ __forceinline__ void mma_bf16(float c[4],
                                         uint32_t a0, uint32_t a1, uint32_t a2, uint32_t a3,
                                         uint32_t b0, uint32_t b1) {
    asm volatile(
        "mma.sync.aligned.m16n8k16.row.col.f32.bf16.bf16.f32 "
        "{%0,%1,%2,%3}, {%4,%5,%6,%7}, {%8,%9}, {%0,%1,%2,%3};"
        : "+f"(c[0]), "+f"(c[1]), "+f"(c[2]), "+f"(c[3])
        : "r"(a0), "r"(a1), "r"(a2), "r"(a3), "r"(b0), "r"(b1));
}
__device__ __forceinline__ void ldsm4(uint32_t &r0, uint32_t &r1, uint32_t &r2, uint32_t &r3,
                                      uint32_t addr) {
    asm volatile("ldmatrix.sync.aligned.m8n8.x4.shared.b16 {%0,%1,%2,%3}, [%4];"
                 : "=r"(r0), "=r"(r1), "=r"(r2), "=r"(r3) : "r"(addr));
}

// ---------------- split-bf16 HMMA GEMM (3-stage pipeline) ----------------
// C[2048, N] = A * B^T ; A hi/lo [M,K] k-major, B hi/lo [N,K] k-major. f32 C out.
// BM=128 BN=128 BK=64, 256 threads, 8 warps (2x4), warp tile 64x32.
// 3-stage cp.async pipeline (192 KB smem), one __syncthreads per stage.
// bx >= n1tiles selects second matrix (B2/C2). causal 1: skip bx>by.
#define TILE_BYTES 16384
#define STAGE_BYTES 65536
#define NSTG 3

__global__ void __launch_bounds__(256, 1)
gemm5(const bf16* __restrict__ AhG, const bf16* __restrict__ AlG,
      const bf16* __restrict__ BhG, const bf16* __restrict__ BlG,
      float* __restrict__ CG,
      const bf16* __restrict__ B2h, const bf16* __restrict__ B2l,
      float* __restrict__ C2G,
      int n1tiles, int N1, int N2, int K,
      int lda, int ldb, int ldc, int ldb2, int ldc2,
      long long sA, long long sB, long long sC, int causal)
{
    extern __shared__ uint8_t smem[];
    int bx = blockIdx.x, by = blockIdx.y, bz = blockIdx.z;
    if (causal == 1 && bx > by) return;

    const bf16* Ah = AhG + bz * sA;
    const bf16* Al = AlG + bz * sA;
    const bf16* Bh; const bf16* Bl; float* C;
    int n, ldbv, ldcv;
    if (bx < n1tiles) {
        Bh = BhG + bz * sB; Bl = BlG + bz * sB; C = CG + bz * sC;
        n = N1; ldbv = ldb; ldcv = ldc;
    } else {
        bx -= n1tiles;
        Bh = B2h; Bl = B2l; C = C2G;
        n = N2; ldbv = ldb2; ldcv = ldc2;
    }

    int iters = K >> 6;

    int tid = threadIdx.x, lane = tid & 31, warp = tid >> 5;
    int wm = warp & 1, wn = warp >> 1;

    int lrow = tid >> 1;
    int lc4  = (tid & 1) * 4;
    const bf16* aHp = Ah + (size_t)(by * 128 + lrow) * lda;
    const bf16* aLp = Al + (size_t)(by * 128 + lrow) * lda;
    int gn = bx * 128 + lrow;
    int bvalid = (gn < n) ? 16 : 0;
    int gcl = (gn < n) ? gn : 0;
    const bf16* bHp = Bh + (size_t)gcl * ldbv;
    const bf16* bLp = Bl + (size_t)gcl * ldbv;

    uint32_t sb = (uint32_t)__cvta_generic_to_shared(smem);
    uint32_t soff[4];
    #pragma unroll
    for (int c = 0; c < 4; c++)
        soff[c] = lrow * 128 + (((lc4 + c) ^ (lrow & 7)) << 4);

    auto load_stage = [&](int kb, int st) {
        uint32_t base = sb + st * STAGE_BYTES;
        #pragma unroll
        for (int c = 0; c < 4; c++) {
            int ko = kb + (lc4 + c) * 8;
            asm volatile("cp.async.cg.shared.global [%0], [%1], 16;"
                         :: "r"(base + soff[c]), "l"(aHp + ko));
            asm volatile("cp.async.cg.shared.global [%0], [%1], 16;"
                         :: "r"(base + TILE_BYTES + soff[c]), "l"(aLp + ko));
            asm volatile("cp.async.cg.shared.global [%0], [%1], 16, %2;"
                         :: "r"(base + 2*TILE_BYTES + soff[c]), "l"(bHp + ko), "r"(bvalid));
            asm volatile("cp.async.cg.shared.global [%0], [%1], 16, %2;"
                         :: "r"(base + 3*TILE_BYTES + soff[c]), "l"(bLp + ko), "r"(bvalid));
        }
        asm volatile("cp.async.commit_group;");
    };

    uint32_t aOff[4]; int aSw[4];
    #pragma unroll
    for (int mt = 0; mt < 4; mt++) {
        int r = wm * 64 + mt * 16 + (lane & 15);
        aOff[mt] = r * 128; aSw[mt] = r & 7;
    }
    uint32_t bOff[2]; int bSw[2];
    #pragma unroll
    for (int np = 0; np < 2; np++) {
        int r = wn * 32 + np * 16 + (lane & 7) + ((lane & 16) ? 8 : 0);
        bOff[np] = r * 128; bSw[np] = r & 7;
    }
    int aHalf = lane >> 4;
    int bHalf = (lane >> 3) & 1;

    float acc[4][4][4] = {};

    // prologue: fill 2 stages
    load_stage(0, 0);
    if (iters > 1) load_stage(64, 1);

    for (int it = 0; it < iters; ++it) {
        int s = it % NSTG;
        if (it + 1 < iters) asm volatile("cp.async.wait_group 1;");
        else                asm volatile("cp.async.wait_group 0;");
        __syncthreads();
        if (it + 2 < iters) load_stage((it + 2) * 64, (it + 2) % NSTG);

        uint32_t Ab = sb + s * STAGE_BYTES;
        uint32_t Bb = Ab + 2 * TILE_BYTES;
        #pragma unroll
        for (int ks = 0; ks < 4; ks++) {
            uint32_t aHf[4][4], aLf[4][4], bHf[2][4], bLf[2][4];
            int ca = 2 * ks + aHalf;
            int cb = 2 * ks + bHalf;
            #pragma unroll
            for (int mt = 0; mt < 4; mt++) {
                uint32_t ad = Ab + aOff[mt] + (((uint32_t)(ca ^ aSw[mt])) << 4);
                ldsm4(aHf[mt][0], aHf[mt][1], aHf[mt][2], aHf[mt][3], ad);
                ldsm4(aLf[mt][0], aLf[mt][1], aLf[mt][2], aLf[mt][3], ad + TILE_BYTES);
            }
            #pragma unroll
            for (int np = 0; np < 2; np++) {
                uint32_t bd = Bb + bOff[np] + (((uint32_t)(cb ^ bSw[np])) << 4);
                ldsm4(bHf[np][0], bHf[np][1], bHf[np][2], bHf[np][3], bd);
                ldsm4(bLf[np][0], bLf[np][1], bLf[np][2], bLf[np][3], bd + TILE_BYTES);
            }
            #pragma unroll
            for (int mt = 0; mt < 4; mt++)
                #pragma unroll
                for (int nt = 0; nt < 4; nt++) {
                    int np = nt >> 1, hf = (nt & 1) * 2;
                    mma_bf16(acc[mt][nt], aLf[mt][0], aLf[mt][1], aLf[mt][2], aLf[mt][3],
                             bHf[np][hf], bHf[np][hf + 1]);
                }
            #pragma unroll
            for (int mt = 0; mt < 4; mt++)
                #pragma unroll
                for (int nt = 0; nt < 4; nt++) {
                    int np = nt >> 1, hf = (nt & 1) * 2;
                    mma_bf16(acc[mt][nt], aHf[mt][0], aHf[mt][1], aHf[mt][2], aHf[mt][3],
                             bLf[np][hf], bLf[np][hf + 1]);
                }
            #pragma unroll
            for (int mt = 0; mt < 4; mt++)
                #pragma unroll
                for (int nt = 0; nt < 4; nt++) {
                    int np = nt >> 1, hf = (nt & 1) * 2;
                    mma_bf16(acc[mt][nt], aHf[mt][0], aHf[mt][1], aHf[mt][2], aHf[mt][3],
                             bHf[np][hf], bHf[np][hf + 1]);
                }
        }
    }

    int g = lane >> 2, tg = lane & 3;
    #pragma unroll
    for (int mt = 0; mt < 4; mt++) {
        int r0 = by * 128 + wm * 64 + mt * 16 + g;
        #pragma unroll
        for (int nt = 0; nt < 4; nt++) {
            int col = bx * 128 + wn * 32 + nt * 8 + 2 * tg;
            if (col < n) {
                *reinterpret_cast<float2*>(C + (size_t)r0 * ldcv + col) =
                    make_float2(acc[mt][nt][0], acc[mt][nt][1]);
                *reinterpret_cast<float2*>(C + (size_t)(r0 + 8) * ldcv + col) =
                    make_float2(acc[mt][nt][2], acc[mt][nt][3]);
            }
        }
    }
}

// ---------------- PV GEMM: A = f32 P (inline split), B = split VT, C = split bf16 ----------------
#define PVBUF 8192
#define PVSTG 32768

__global__ void __launch_bounds__(256, 1)
gemm_pv(const float* __restrict__ Pf, const bf16* __restrict__ VThG,
        const bf16* __restrict__ VTlG, bf16* __restrict__ ChG, bf16* __restrict__ ClG)
{
    extern __shared__ uint8_t smem[];
    int by = blockIdx.x, h = blockIdx.y;

    const float* P  = Pf  + (size_t)h * S_LEN * S_LEN;
    const bf16* VTh = VThG + (size_t)h * V_D * S_LEN;
    const bf16* VTl = VTlG + (size_t)h * V_D * S_LEN;
    bf16* Ch = ChG + h * V_D;
    bf16* Cl = ClG + h * V_D;

    int iters = (by + 1) * 4;

    int tid = threadIdx.x, lane = tid & 31, warp = tid >> 5;
    int wm = warp & 1, wn = warp >> 1;

    int a_row = tid >> 1;
    int a_c0  = (tid & 1) * 16;
    const float* aP = P + (size_t)(by * 128 + a_row) * S_LEN + a_c0;
    int b_row = tid >> 1;
    int b_ch0 = (tid & 1) * 2;
    const bf16* bHp = VTh + (size_t)b_row * S_LEN;
    const bf16* bLp = VTl + (size_t)b_row * S_LEN;

    uint32_t sb = (uint32_t)__cvta_generic_to_shared(smem);
    int aswz = (a_row >> 1) & 3;
    int bswz = (b_row >> 1) & 3;
    uint32_t bso[2];
    #pragma unroll
    for (int c = 0; c < 2; c++)
        bso[c] = b_row * 64 + (((b_ch0 + c) ^ bswz) << 4);

    auto loadB = [&](int it, int st) {
        uint32_t base = sb + st * PVSTG + 2 * PVBUF;
        int ko = it * 32 + b_ch0 * 8;
        asm volatile("cp.async.cg.shared.global [%0], [%1], 16;"
                     :: "r"(base + bso[0]), "l"(bHp + ko));
        asm volatile("cp.async.cg.shared.global [%0], [%1], 16;"
                     :: "r"(base + bso[0] + PVBUF), "l"(bLp + ko));
        asm volatile("cp.async.cg.shared.global [%0], [%1], 16;"
                     :: "r"(base + bso[1]), "l"(bHp + ko + 8));
        asm volatile("cp.async.cg.shared.global [%0], [%1], 16;"
                     :: "r"(base + bso[1] + PVBUF), "l"(bLp + ko + 8));
        asm volatile("cp.async.commit_group;");
    };

    uint32_t aOff[4]; int aSw[4];
    #pragma unroll
    for (int mt = 0; mt < 4; mt++) {
        int r = wm * 64 + mt * 16 + (lane & 15);
        aOff[mt] = r * 64; aSw[mt] = (r >> 1) & 3;
    }
    uint32_t bOff[2]; int bSw[2];
    #pragma unroll
    for (int np = 0; np < 2; np++) {
        int r = wn * 32 + np * 16 + (lane & 7) + ((lane & 16) ? 8 : 0);
        bOff[np] = r * 64; bSw[np] = (r >> 1) & 3;
    }
    int aHalf = lane >> 4;
    int bHalf = (lane >> 3) & 1;

    float acc[4][4][4] = {};
    float4 ar[4];

    loadB(0, 0);
    #pragma unroll
    for (int v = 0; v < 4; v++)
        ar[v] = *reinterpret_cast<const float4*>(aP + v * 4);

    for (int it = 0; it < iters; ++it) {
        int s = it & 1;
        __syncthreads();
        {
            uint32_t abase = sb + s * PVSTG;
            uint32_t hi[8], lo[8];
            #pragma unroll
            for (int v = 0; v < 4; v++) {
                hi[2*v]   = split2(ar[v].x, ar[v].y, lo[2*v]);
                hi[2*v+1] = split2(ar[v].z, ar[v].w, lo[2*v+1]);
            }
            int ch0 = a_c0 >> 3;
            #pragma unroll
            for (int c = 0; c < 2; c++) {
                uint32_t ad = abase + a_row * 64 + (((ch0 + c) ^ aswz) << 4);
                asm volatile("st.shared.v4.b32 [%0], {%1,%2,%3,%4};"
                             :: "r"(ad), "r"(hi[4*c]), "r"(hi[4*c+1]),
                                "r"(hi[4*c+2]), "r"(hi[4*c+3]));
                asm volatile("st.shared.v4.b32 [%0], {%1,%2,%3,%4};"
                             :: "r"(ad + PVBUF), "r"(lo[4*c]), "r"(lo[4*c+1]),
                                "r"(lo[4*c+2]), "r"(lo[4*c+3]));
            }
        }
        if (it + 1 < iters) {
            loadB(it + 1, s ^ 1);
            #pragma unroll
            for (int v = 0; v < 4; v++)
                ar[v] = *reinterpret_cast<const float4*>(aP + (it + 1) * 32 + v * 4);
            asm volatile("cp.async.wait_group 1;");
        } else {
            asm volatile("cp.async.wait_group 0;");
        }
        __syncthreads();

        uint32_t Ab = sb + s * PVSTG;
        uint32_t Bb = Ab + 2 * PVBUF;
        #pragma unroll
        for (int ks = 0; ks < 2; ks++) {
            uint32_t aH[4][4], aL[4][4], bH[2][4], bL[2][4];
            int ca = 2 * ks + aHalf;
            int cb = 2 * ks + bHalf;
            #pragma unroll
            for (int mt = 0; mt < 4; mt++) {
                uint32_t ad = Ab + aOff[mt] + (((uint32_t)(ca ^ aSw[mt])) << 4);
                ldsm4(aH[mt][0], aH[mt][1], aH[mt][2], aH[mt][3], ad);
                ldsm4(aL[mt][0], aL[mt][1], aL[mt][2], aL[mt][3], ad + PVBUF);
            }
            #pragma unroll
            for (int np = 0; np < 2; np++) {
                uint32_t bd = Bb + bOff[np] + (((uint32_t)(cb ^ bSw[np])) << 4);
                ldsm4(bH[np][0], bH[np][1], bH[np][2], bH[np][3], bd);
                ldsm4(bL[np][0], bL[np][1], bL[np][2], bL[np][3], bd + PVBUF);
            }
            #pragma unroll
            for (int mt = 0; mt < 4; mt++)
                #pragma unroll
                for (int nt = 0; nt < 4; nt++) {
                    int np = nt >> 1, hf = (nt & 1) * 2;
                    mma_bf16(acc[mt][nt], aL[mt][0], aL[mt][1], aL[mt][2], aL[mt][3],
                             bH[np][hf], bH[np][hf + 1]);
                }
            #pragma unroll
            for (int mt = 0; mt < 4; mt++)
                #pragma unroll
                for (int nt = 0; nt < 4; nt++) {
                    int np = nt >> 1, hf = (nt & 1) * 2;
                    mma_bf16(acc[mt][nt], aH[mt][0], aH[mt][1], aH[mt][2], aH[mt][3],
                             bL[np][hf], bL[np][hf + 1]);
                }
            #pragma unroll
            for (int mt = 0; mt < 4; mt++)
                #pragma unroll
                for (int nt = 0; nt < 4; nt++) {
                    int np = nt >> 1, hf = (nt & 1) * 2;
                    mma_bf16(acc[mt][nt], aH[mt][0], aH[mt][1], aH[mt][2], aH[mt][3],
                             bH[np][hf], bH[np][hf + 1]);
                }
        }
    }

    int g = lane >> 2, tg = lane & 3;
    #pragma unroll
    for (int mt = 0; mt < 4; mt++) {
        int r0 = by * 128 + wm * 64 + mt * 16 + g;
        #pragma unroll
        for (int nt = 0; nt < 4; nt++) {
            int col = wn * 32 + nt * 8 + 2 * tg;
            uint32_t lo0, lo1;
            uint32_t hi0 = split2(acc[mt][nt][0], acc[mt][nt][1], lo0);
            uint32_t hi1 = split2(acc[mt][nt][2], acc[mt][nt][3], lo1);
            *reinterpret_cast<uint32_t*>(Ch + (size_t)r0 * HDIM + col) = hi0;
            *reinterpret_cast<uint32_t*>(Cl + (size_t)r0 * HDIM + col) = lo0;
            *reinterpret_cast<uint32_t*>(Ch + (size_t)(r0 + 8) * HDIM + col) = hi1;
            *reinterpret_cast<uint32_t*>(Cl + (size_t)(r0 + 8) * HDIM + col) = lo1;
        }
    }
}

// ---------------- f32 -> split bf16 conversion ----------------
__global__ void convert_split(const float* __restrict__ s, bf16* __restrict__ h,
                              bf16* __restrict__ l, int n)
{
    int i = (blockIdx.x * 256 + threadIdx.x) * 4;
    if (i < n) {
        float4 v = *reinterpret_cast<const float4*>(s + i);
        uint32_t lo0, lo1;
        uint32_t hi0 = split2(v.x, v.y, lo0);
        uint32_t hi1 = split2(v.z, v.w, lo1);
        *reinterpret_cast<uint32_t*>(h + i)     = hi0;
        *reinterpret_cast<uint32_t*>(l + i)     = lo0;
        *reinterpret_cast<uint32_t*>(h + i + 2) = hi1;
        *reinterpret_cast<uint32_t*>(l + i + 2) = lo1;
    }
}

// ---------------- RMS norm: f32 in-place + split bf16 out ----------------
__global__ void rmsnorm_split_kernel(float* __restrict__ x, const float* __restrict__ w,
                                     bf16* __restrict__ oh, bf16* __restrict__ ol, int n)
{
    float* xr = x + (size_t)blockIdx.x * n;
    bf16* hr = oh + (size_t)blockIdx.x * n;
    bf16* lr = ol + (size_t)blockIdx.x * n;
    __shared__ float red[256];
    int t = threadIdx.x;
    float s = 0.f;
    for (int i = t; i < n; i += 256) { float v = xr[i]; s += v * v; }
    red[t] = s; __syncthreads();
    for (int k = 128; k > 0; k >>= 1) { if (t < k) red[t] += red[t + k]; __syncthreads(); }
    float inv = 1.0f / sqrtf(red[0] / (float)n + 1e-6f);
    for (int i = t; i < n; i += 256) {
        float v = w[i] * (xr[i] * inv);
        xr[i] = v;
        bf16 h, l; split1(v, h, l);
        hr[i] = h; lr[i] = l;
    }
}

// ---------------- RoPE + assemble split Q/K ----------------
__global__ void rope_assemble_kernel()
{
    int s = blockIdx.x;
    int t = threadIdx.x;
    __shared__ float cs[32], sn[32], kr[64];

    if (t < 32) {
        float invf = (float)exp(-(double)t / 32.0 * log(10000.0));
        float ang  = (float)s * invf;
        double a = (double)ang;
        float c = (float)cos(a), si = (float)sin(a);
        cs[t] = c; sn[t] = si;
        float x0 = g_ckv[(size_t)s * CKV_W + KVLAT + 2 * t];
        float x1 = g_ckv[(size_t)s * CKV_W + KVLAT + 2 * t + 1];
        kr[t]      = x0 * c - x1 * si;
        kr[t + 32] = x1 * c + x0 * si;
    }
    __syncthreads();

    for (int idx = t; idx < NHEAD * 32; idx += 256) {
        int h = idx >> 5, j = idx & 31;
        float x0 = g_qup[(size_t)s * QUP_W + h * 192 + 128 + 2 * j];
        float x1 = g_qup[(size_t)s * QUP_W + h * 192 + 128 + 2 * j + 1];
        size_t base = ((size_t)h * S_LEN + s) * QK_D;
        bf16 hh, ll;
        split1(x0 * cs[j] - x1 * sn[j], hh, ll); g_Qh[base + j] = hh;      g_Ql[base + j] = ll;
        split1(x1 * cs[j] + x0 * sn[j], hh, ll); g_Qh[base + j + 32] = hh; g_Ql[base + j + 32] = ll;
    }
    for (int idx = t; idx < NHEAD * 64; idx += 256) {
        int h = idx >> 6, j = idx & 63;
        size_t base = ((size_t)h * S_LEN + s) * QK_D;
        bf16 hh, ll; split1(kr[j], hh, ll);
        g_Kh[base + j] = hh; g_Kl[base + j] = ll;
    }
    for (int idx = t; idx < NHEAD * 128; idx += 256) {
        int h = idx >> 7, d = idx & 127;
        size_t base = ((size_t)h * S_LEN + s) * QK_D + 64 + d;
        bf16 hh, ll;
        split1(g_qup[(size_t)s * QUP_W + h * 192 + d], hh, ll);
        g_Qh[base] = hh; g_Ql[base] = ll;
        split1(g_kvup[(size_t)s * KVUP_W + h * 256 + d], hh, ll);
        g_Kh[base] = hh; g_Kl[base] = ll;
    }
}

// ---------------- V transpose + split: kvup -> VT[h][d][s] ----------------
__global__ void vt_kernel()   // grid (64, 4, 16), block (32, 8)
{
    __shared__ float tile[32][33];
    int h = blockIdx.z, s0 = blockIdx.x * 32, d0 = blockIdx.y * 32;
    int tx = threadIdx.x, ty = threadIdx.y;
    #pragma unroll
    for (int j = 0; j < 4; j++) {
        int srow = s0 + ty + 8 * j;
        tile[ty + 8 * j][tx] = g_kvup[(size_t)srow * KVUP_W + h * 256 + 128 + d0 + tx];
    }
    __syncthreads();
    #pragma unroll
    for (int j = 0; j < 4; j++) {
        int d = d0 + ty + 8 * j;
        int s = s0 + tx;
        bf16 hh, ll; split1(tile[tx][ty + 8 * j], hh, ll);
        size_t o = ((size_t)h * V_D + d) * S_LEN + s;
        g_VTh[o] = hh; g_VTl[o] = ll;
    }
}

// ---------------- causal softmax: f32 in-place, vectorized ----------------
__global__ void softmax_kernel(float* __restrict__ aw)
{
    int row = blockIdx.x;
    int q = row & (S_LEN - 1);
    float* x = aw + (size_t)row * S_LEN;
    __shared__ float buf[S_LEN];
    __shared__ float red[8];
    int n = q + 1;
    int n4 = n & ~3;
    int t = threadIdx.x;
    int lane = t & 31, wrp = t >> 5;

    float m = -1e30f;
    for (int i = 4 * t; i < n4; i += 1024) {
        float4 v = *reinterpret_cast<const float4*>(x + i);
        *reinterpret_cast<float4*>(buf + i) = v;
        m = fmaxf(m, fmaxf(fmaxf(v.x, v.y), fmaxf(v.z, v.w)));
    }
    for (int i = n4 + t; i < n; i += 256) { float v = x[i]; buf[i] = v; m = fmaxf(m, v); }
    #pragma unroll
    for (int o = 16; o > 0; o >>= 1) m = fmaxf(m, __shfl_xor_sync(0xffffffffu, m, o));
    if (lane == 0) red[wrp] = m;
    __syncthreads();
    m = red[lane & 7];
    #pragma unroll
    for (int o = 4; o > 0; o >>= 1) m = fmaxf(m, __shfl_xor_sync(0xffffffffu, m, o));
    __syncthreads();

    float s = 0.f;
    for (int i = 4 * t; i < n4; i += 1024) {
        float4 v = *reinterpret_cast<float4*>(buf + i);
        v.x = expf(v.x - m); v.y = expf(v.y - m);
        v.z = expf(v.z - m); v.w = expf(v.w - m);
        *reinterpret_cast<float4*>(buf + i) = v;
        s += v.x + v.y + v.z + v.w;
    }
    for (int i = n4 + t; i < n; i += 256) { float e = expf(buf[i] - m); buf[i] = e; s += e; }
    #pragma unroll
    for (int o = 16; o > 0; o >>= 1) s += __shfl_xor_sync(0xffffffffu, s, o);
    if (lane == 0) red[wrp] = s;
    __syncthreads();
    s = red[lane & 7];
    #pragma unroll
    for (int o = 4; o > 0; o >>= 1) s += __shfl_xor_sync(0xffffffffu, s, o);
    float inv = 1.0f / s;

    for (int i = 4 * t; i < S_LEN; i += 1024) {
        float4 v = *reinterpret_cast<float4*>(buf + i);
        float4 p;
        p.x = (i     < n) ? v.x * inv : 0.0f;
        p.y = (i + 1 < n) ? v.y * inv : 0.0f;
        p.z = (i + 2 < n) ? v.z * inv : 0.0f;
        p.w = (i + 3 < n) ? v.w * inv : 0.0f;
        *reinterpret_cast<float4*>(x + i) = p;
    }
}

// ---------------- launch ----------------
extern "C" void kernel_launch(void* const* d_in, const int* in_sizes, int n_in,
                              void* d_out, int out_size)
{
    const float* hidden  = (const float*)d_in[0];
    const float* q_down  = (const float*)d_in[3];
    const float* kv_down = (const float*)d_in[4];
    const float* q_up    = (const float*)d_in[5];
    const float* k_up    = (const float*)d_in[6];
    const float* o_w     = (const float*)d_in[7];
    const float* q_norm  = (const float*)d_in[8];
    const float* kv_norm = (const float*)d_in[9];

    float* out = (float*)d_out;
    float* aw = out;
    float* ao = out + (size_t)NHEAD * S_LEN * S_LEN;

    size_t smem = NSTG * STAGE_BYTES;   // 192 KB
    cudaFuncSetAttribute(gemm5, cudaFuncAttributeMaxDynamicSharedMemorySize, smem);
    cudaFuncSetAttribute(gemm_pv, cudaFuncAttributeMaxDynamicSharedMemorySize, 2 * PVSTG);

    float *cq, *ckv, *qup, *kvup;
    cudaGetSymbolAddress((void**)&cq,   g_cq);
    cudaGetSymbolAddress((void**)&ckv,  g_ckv);
    cudaGetSymbolAddress((void**)&qup,  g_qup);
    cudaGetSymbolAddress((void**)&kvup, g_kvup);
    bf16 *hidh,*hidl,*wqdh,*wqdl,*wkdh,*wkdl,*wquh,*wqul,*wkuh,*wkul,*woh,*wol;
    bf16 *cqh,*cql,*ckvh,*ckvl,*Qh,*Ql,*Kh,*Kl,*VTh,*VTl,*aph,*apl;
    cudaGetSymbolAddress((void**)&hidh, g_hidh); cudaGetSymbolAddress((void**)&hidl, g_hidl);
    cudaGetSymbolAddress((void**)&wqdh, g_wqdh); cudaGetSymbolAddress((void**)&wqdl, g_wqdl);
    cudaGetSymbolAddress((void**)&wkdh, g_wkdh); cudaGetSymbolAddress((void**)&wkdl, g_wkdl);
    cudaGetSymbolAddress((void**)&wquh, g_wquh); cudaGetSymbolAddress((void**)&wqul, g_wqul);
    cudaGetSymbolAddress((void**)&wkuh, g_wkuh); cudaGetSymbolAddress((void**)&wkul, g_wkul);
    cudaGetSymbolAddress((void**)&woh,  g_woh);  cudaGetSymbolAddress((void**)&wol,  g_wol);
    cudaGetSymbolAddress((void**)&cqh,  g_cqh);  cudaGetSymbolAddress((void**)&cql,  g_cql);
    cudaGetSymbolAddress((void**)&ckvh, g_ckvh); cudaGetSymbolAddress((void**)&ckvl, g_ckvl);
    cudaGetSymbolAddress((void**)&Qh,   g_Qh);   cudaGetSymbolAddress((void**)&Ql,   g_Ql);
    cudaGetSymbolAddress((void**)&Kh,   g_Kh);   cudaGetSymbolAddress((void**)&Kl,   g_Kl);
    cudaGetSymbolAddress((void**)&VTh,  g_VTh);  cudaGetSymbolAddress((void**)&VTl,  g_VTl);
    cudaGetSymbolAddress((void**)&aph,  g_aph);  cudaGetSymbolAddress((void**)&apl,  g_apl);

    dim3 blk(256);
    auto cgrid = [](size_t n) { return (unsigned)((n / 4 + 255) / 256); };

    // 0) split conversions
    convert_split<<<cgrid((size_t)S_LEN*HDIM),   blk>>>(hidden,  hidh, hidl, S_LEN*HDIM);
    convert_split<<<cgrid((size_t)QLAT*HDIM),    blk>>>(q_down,  wqdh, wqdl, QLAT*HDIM);
    convert_split<<<cgrid((size_t)CKV_W*HDIM),   blk>>>(kv_down, wkdh, wkdl, CKV_W*HDIM);
    convert_split<<<cgrid((size_t)QUP_W*QLAT),   blk>>>(q_up,    wquh, wqul, QUP_W*QLAT);
    convert_split<<<cgrid((size_t)KVUP_W*KVLAT), blk>>>(k_up,    wkuh, wkul, KVUP_W*KVLAT);
    convert_split<<<cgrid((size_t)HDIM*HDIM),    blk>>>(o_w,     woh,  wol,  HDIM*HDIM);

    // 1) fused down projections (q_down 12 tiles + kv_down 5 tiles)
    gemm5<<<dim3(17, 16), blk, smem>>>(
        hidh, hidl, wqdh, wqdl, cq,
        wkdh, wkdl, ckv,
        12, QLAT, CKV_W, HDIM,
        HDIM, HDIM, QLAT, HDIM, CKV_W, 0, 0, 0, 0);

    // 2) RMS norms
    rmsnorm_split_kernel<<<S_LEN, blk>>>(cq,  q_norm,  cqh,  cql,  QLAT);
    rmsnorm_split_kernel<<<S_LEN, blk>>>(ckv, kv_norm, ckvh, ckvl, CKV_W);

    // 3) up projections
    gemm5<<<dim3(QUP_W/128, 16), blk, smem>>>(
        cqh, cql, wquh, wqul, qup,
        nullptr, nullptr, nullptr,
        1 << 20, QUP_W, 0, QLAT,
        QLAT, QLAT, QUP_W, 0, 0, 0, 0, 0, 0);
    gemm5<<<dim3(KVUP_W/128, 16), blk, smem>>>(
        ckvh, ckvl, wkuh, wkul, kvup,
        nullptr, nullptr, nullptr,
        1 << 20, KVUP_W, 0, KVLAT,
        CKV_W, KVLAT, KVUP_W, 0, 0, 0, 0, 0, 0);

    // 4) RoPE + assembly, V transpose
    rope_assemble_kernel<<<S_LEN, blk>>>();
    vt_kernel<<<dim3(64, 4, 16), dim3(32, 8)>>>();

    // 5) logits S = Q K^T (causal tile skip), f32 into d_out
    gemm5<<<dim3(16, 16, 16), blk, smem>>>(
        Qh, Ql, Kh, Kl, aw,
        nullptr, nullptr, nullptr,
        1 << 20, S_LEN, 0, QK_D,
        QK_D, QK_D, S_LEN, 0, 0,
        (long long)S_LEN*QK_D, (long long)S_LEN*QK_D, (long long)S_LEN*S_LEN, 1);

    // 6) softmax (f32 in-place, vectorized)
    softmax_kernel<<<NHEAD * S_LEN, blk>>>(aw);

    // 7) O = P @ V: read f32 P, inline split, split bf16 out
    gemm_pv<<<dim3(16, 16), blk, 2 * PVSTG>>>(aw, VTh, VTl, aph, apl);

    // 8) final output projection (f32 into d_out)
    gemm5<<<dim3(16, 16), blk, smem>>>(
        aph, apl, woh, wol, ao,
        nullptr, nullptr, nullptr,
        1 << 20, HDIM, 0, HDIM,
        HDIM, HDIM, HDIM, 0, 0, 0, 0, 0, 0);
}